// round 4
// baseline (speedup 1.0000x reference)
#include <cuda_runtime.h>
#include <cuda_bf16.h>

#define N_NODES 100000
#define N_EDGES 1600000

// ---- scratch (device globals: no allocation allowed) ----
__device__ int   g_cnt [N_NODES];
__device__ int   g_off [N_NODES];
__device__ int   g_cur [N_NODES];
__device__ int   g_ssrc[N_EDGES];
__device__ float g_h1  [(size_t)N_NODES * 128];
__device__ float g_agg2[(size_t)N_NODES * 128];
__device__ float g_pool[128];

// ---------------------------------------------------------------------------
// 1) init: zero histogram + pool accumulator
__global__ void k_init() {
    int i = blockIdx.x * blockDim.x + threadIdx.x;
    if (i < N_NODES) g_cnt[i] = 0;
    if (i < 128)     g_pool[i] = 0.f;
}

// 2) histogram of dst
__global__ void k_hist(const int* __restrict__ ei) {
    int e = blockIdx.x * blockDim.x + threadIdx.x;
    if (e < N_EDGES) atomicAdd(&g_cnt[ei[N_EDGES + e]], 1);
}

// 3) single-block exclusive scan of g_cnt -> g_off (and copy to g_cur)
__global__ void k_scan() {
    __shared__ int wsum[32];
    int t = threadIdx.x, lane = t & 31, w = t >> 5;
    int carry = 0;
    for (int base = 0; base < N_NODES; base += 1024) {
        int i = base + t;
        int v = (i < N_NODES) ? g_cnt[i] : 0;
        int xv = v;
        #pragma unroll
        for (int d = 1; d < 32; d <<= 1) {
            int y = __shfl_up_sync(0xffffffffu, xv, d);
            if (lane >= d) xv += y;
        }
        if (lane == 31) wsum[w] = xv;
        __syncthreads();
        if (w == 0) {
            int y = wsum[lane];
            #pragma unroll
            for (int d = 1; d < 32; d <<= 1) {
                int z = __shfl_up_sync(0xffffffffu, y, d);
                if (lane >= d) y += z;
            }
            wsum[lane] = y;
        }
        __syncthreads();
        int excl = xv - v + (w > 0 ? wsum[w - 1] : 0) + carry;
        if (i < N_NODES) { g_off[i] = excl; g_cur[i] = excl; }
        carry += wsum[31];
        __syncthreads();
    }
}

// 4) scatter src indices into dst-sorted order (counting sort)
__global__ void k_scatter(const int* __restrict__ ei) {
    int e = blockIdx.x * blockDim.x + threadIdx.x;
    if (e < N_EDGES) {
        int d = ei[N_EDGES + e];
        int p = atomicAdd(&g_cur[d], 1);
        g_ssrc[p] = ei[e];
    }
}

// 5) layer 1 fused: CSR-aggregate x (4-dim) + h1 = relu(agg@W1_rel^T + b1 + x@W1_root^T)
__global__ void k_h1(const float* __restrict__ x,
                     const float* __restrict__ W1_rel,
                     const float* __restrict__ b1,
                     const float* __restrict__ W1_root) {
    __shared__ float sWr[512], sWo[512], sb[128];
    int t = threadIdx.x;  // 128 threads
    sb[t] = b1[t];
    #pragma unroll
    for (int r = 0; r < 4; r++) {
        sWr[t + 128 * r] = W1_rel[t + 128 * r];
        sWo[t + 128 * r] = W1_root[t + 128 * r];
    }
    __syncthreads();
    int n = blockIdx.x * 128 + t;
    if (n >= N_NODES) return;

    const float4* x4 = (const float4*)x;
    float4 xi = x4[n];
    float4 ag = make_float4(0.f, 0.f, 0.f, 0.f);
    int s0 = g_off[n], c = g_cnt[n];
    for (int i = 0; i < c; i++) {
        int s = g_ssrc[s0 + i];
        float4 v = x4[s];
        ag.x += v.x; ag.y += v.y; ag.z += v.z; ag.w += v.w;
    }
    float4* out = (float4*)(g_h1 + (size_t)n * 128);
    #pragma unroll
    for (int j4 = 0; j4 < 32; j4++) {
        float o[4];
        #pragma unroll
        for (int u = 0; u < 4; u++) {
            int j = j4 * 4 + u;
            float v = sb[j];
            v += ag.x * sWr[j * 4 + 0] + ag.y * sWr[j * 4 + 1]
               + ag.z * sWr[j * 4 + 2] + ag.w * sWr[j * 4 + 3];
            v += xi.x * sWo[j * 4 + 0] + xi.y * sWo[j * 4 + 1]
               + xi.z * sWo[j * 4 + 2] + xi.w * sWo[j * 4 + 3];
            o[u] = fmaxf(v, 0.f);
        }
        out[j4] = make_float4(o[0], o[1], o[2], o[3]);
    }
}

// 6) layer 2 aggregation: warp per node, atomic-free CSR sum of h1 rows
__global__ void k_agg2() {
    int gtid = blockIdx.x * blockDim.x + threadIdx.x;
    int node = gtid >> 5;
    int lane = gtid & 31;
    if (node >= N_NODES) return;
    int s0 = g_off[node], c = g_cnt[node];
    const float4* h1v = (const float4*)g_h1;
    float4 acc = make_float4(0.f, 0.f, 0.f, 0.f);
    for (int i = 0; i < c; i++) {
        int s = g_ssrc[s0 + i];               // broadcast load across warp
        float4 v = h1v[(size_t)s * 32 + lane];
        acc.x += v.x; acc.y += v.y; acc.z += v.z; acc.w += v.w;
    }
    ((float4*)g_agg2)[(size_t)node * 32 + lane] = acc;
}

// 7) layer 2 GEMM + bias + relu + fused mean-pool accumulation
//    C[n,j] = relu( sum_k agg2[n,k]*W2_rel[j,k] + sum_k h1[n,k]*W2_root[j,k] + b2[j] )
//    pool[j] += sum_n C[n,j]
#define BM 128
#define BN 128
#define BK 16
#define TM 8
#define TN 8
__global__ void k_gemm(const float* __restrict__ W2_rel,
                       const float* __restrict__ W2_root,
                       const float* __restrict__ b2) {
    __shared__ float As[BK][BM];
    __shared__ float Bs[BK][BN];
    __shared__ float poolbuf[BN];

    int block_m = blockIdx.x * BM;
    int ltid = threadIdx.x;        // 256 threads
    int tx = ltid % 16;            // output-col group
    int ty = ltid / 16;            // node-row group

    float acc[TM][TN];
    #pragma unroll
    for (int i = 0; i < TM; i++)
        #pragma unroll
        for (int j = 0; j < TN; j++) acc[i][j] = 0.f;

    for (int kt = 0; kt < 256; kt += BK) {
        const float* Asrc = (kt < 128) ? g_agg2 : g_h1;
        const float* Bsrc = (kt < 128) ? W2_rel : W2_root;
        int kbase = kt & 127;
        #pragma unroll
        for (int r = 0; r < 2; r++) {
            int f = ltid + r * 256;          // 0..511 float4 slots (128 rows x 4)
            int row = f >> 2;
            int cv = (f & 3) * 4;
            int gm = block_m + row;
            float4 va = make_float4(0.f, 0.f, 0.f, 0.f);
            if (gm < N_NODES) va = *(const float4*)(Asrc + (size_t)gm * 128 + kbase + cv);
            As[cv + 0][row] = va.x; As[cv + 1][row] = va.y;
            As[cv + 2][row] = va.z; As[cv + 3][row] = va.w;
            float4 vb = *(const float4*)(Bsrc + (size_t)row * 128 + kbase + cv);
            Bs[cv + 0][row] = vb.x; Bs[cv + 1][row] = vb.y;
            Bs[cv + 2][row] = vb.z; Bs[cv + 3][row] = vb.w;
        }
        __syncthreads();
        #pragma unroll
        for (int k = 0; k < BK; k++) {
            float4 a0 = *(const float4*)&As[k][ty * TM];
            float4 a1 = *(const float4*)&As[k][ty * TM + 4];
            float4 b0 = *(const float4*)&Bs[k][tx * TN];
            float4 b1v = *(const float4*)&Bs[k][tx * TN + 4];
            float a[TM] = {a0.x, a0.y, a0.z, a0.w, a1.x, a1.y, a1.z, a1.w};
            float b[TN] = {b0.x, b0.y, b0.z, b0.w, b1v.x, b1v.y, b1v.z, b1v.w};
            #pragma unroll
            for (int i = 0; i < TM; i++)
                #pragma unroll
                for (int j = 0; j < TN; j++) acc[i][j] += a[i] * b[j];
        }
        __syncthreads();
    }

    if (ltid < BN) poolbuf[ltid] = 0.f;
    __syncthreads();

    float bias[TN];
    #pragma unroll
    for (int j = 0; j < TN; j++) bias[j] = b2[tx * TN + j];

    float psum[TN];
    #pragma unroll
    for (int j = 0; j < TN; j++) psum[j] = 0.f;
    #pragma unroll
    for (int i = 0; i < TM; i++) {
        int gm = block_m + ty * TM + i;
        bool valid = gm < N_NODES;
        #pragma unroll
        for (int j = 0; j < TN; j++) {
            float vv = fmaxf(acc[i][j] + bias[j], 0.f);
            if (valid) psum[j] += vv;
        }
    }
    #pragma unroll
    for (int j = 0; j < TN; j++) atomicAdd(&poolbuf[tx * TN + j], psum[j]);
    __syncthreads();
    if (ltid < BN) atomicAdd(&g_pool[ltid], poolbuf[ltid]);
}

// 8) final head: out = (pool/N) @ Wlin^T + blin
__global__ void k_final(const float* __restrict__ Wlin,
                        const float* __restrict__ blin,
                        float* __restrict__ out) {
    __shared__ float s0[128], s1[128];
    int l = threadIdx.x;  // 128 threads
    float g = g_pool[l] * (1.0f / (float)N_NODES);
    s0[l] = g * Wlin[l];
    s1[l] = g * Wlin[128 + l];
    __syncthreads();
    for (int st = 64; st > 0; st >>= 1) {
        if (l < st) { s0[l] += s0[l + st]; s1[l] += s1[l + st]; }
        __syncthreads();
    }
    if (l == 0) {
        out[0] = s0[0] + blin[0];
        out[1] = s1[0] + blin[1];
    }
}

// ---------------------------------------------------------------------------
extern "C" void kernel_launch(void* const* d_in, const int* in_sizes, int n_in,
                              void* d_out, int out_size) {
    const float* x       = (const float*)d_in[0];
    const int*   ei      = (const int*)  d_in[1];
    const float* W1_rel  = (const float*)d_in[2];
    const float* b1      = (const float*)d_in[3];
    const float* W1_root = (const float*)d_in[4];
    const float* W2_rel  = (const float*)d_in[5];
    const float* b2      = (const float*)d_in[6];
    const float* W2_root = (const float*)d_in[7];
    const float* Wlin    = (const float*)d_in[8];
    const float* blin    = (const float*)d_in[9];
    float* out = (float*)d_out;

    k_init   <<<(N_NODES + 255) / 256, 256>>>();
    k_hist   <<<(N_EDGES + 255) / 256, 256>>>(ei);
    k_scan   <<<1, 1024>>>();
    k_scatter<<<(N_EDGES + 255) / 256, 256>>>(ei);
    k_h1     <<<(N_NODES + 127) / 128, 128>>>(x, W1_rel, b1, W1_root);
    k_agg2   <<<(N_NODES * 32 + 255) / 256, 256>>>();
    k_gemm   <<<(N_NODES + BM - 1) / BM, 256>>>(W2_rel, W2_root, b2);
    k_final  <<<1, 128>>>(Wlin, blin, out);
}

// round 9
// speedup vs baseline: 1.4924x; 1.4924x over previous
#include <cuda_runtime.h>
#include <cuda_bf16.h>
#include <cstdint>

#define N_NODES 100000
#define N_EDGES 1600000

// ---- scratch (device globals: no allocation allowed) ----
__device__ int   g_cnt [N_NODES];
__device__ int   g_off [N_NODES];
__device__ int   g_cur [N_NODES];
__device__ int   g_ssrc[N_EDGES];
__device__ float g_h1  [(size_t)N_NODES * 128];
__device__ float g_agg2[(size_t)N_NODES * 128];
__device__ float g_pool[128];

__device__ __forceinline__ uint32_t cvt_tf32_rna(float f) {
    uint32_t r;
    asm("cvt.rna.tf32.f32 %0, %1;" : "=r"(r) : "f"(f));
    return r;
}

// m16n8k8 tf32 HMMA, fp32 accumulate (sm_80+, valid on plain sm_103 target)
__device__ __forceinline__ void mma_tf32(float* c,
                                         uint32_t a0, uint32_t a1, uint32_t a2, uint32_t a3,
                                         uint32_t b0, uint32_t b1) {
    asm volatile(
        "mma.sync.aligned.m16n8k8.row.col.f32.tf32.tf32.f32 "
        "{%0,%1,%2,%3}, {%4,%5,%6,%7}, {%8,%9}, {%0,%1,%2,%3};"
        : "+f"(c[0]), "+f"(c[1]), "+f"(c[2]), "+f"(c[3])
        : "r"(a0), "r"(a1), "r"(a2), "r"(a3), "r"(b0), "r"(b1));
}

// ---------------------------------------------------------------------------
// 1) init: zero histogram + pool accumulator
__global__ void k_init() {
    int i = blockIdx.x * blockDim.x + threadIdx.x;
    if (i < N_NODES) g_cnt[i] = 0;
    if (i < 128)     g_pool[i] = 0.f;
}

// 2) histogram of dst
__global__ void k_hist(const int* __restrict__ ei) {
    int e = blockIdx.x * blockDim.x + threadIdx.x;
    if (e < N_EDGES) atomicAdd(&g_cnt[ei[N_EDGES + e]], 1);
}

// 3) single-block exclusive scan of g_cnt -> g_off (and copy to g_cur)
__global__ void k_scan() {
    __shared__ int wsum[32];
    int t = threadIdx.x, lane = t & 31, w = t >> 5;
    int carry = 0;
    for (int base = 0; base < N_NODES; base += 1024) {
        int i = base + t;
        int v = (i < N_NODES) ? g_cnt[i] : 0;
        int xv = v;
        #pragma unroll
        for (int d = 1; d < 32; d <<= 1) {
            int y = __shfl_up_sync(0xffffffffu, xv, d);
            if (lane >= d) xv += y;
        }
        if (lane == 31) wsum[w] = xv;
        __syncthreads();
        if (w == 0) {
            int y = wsum[lane];
            #pragma unroll
            for (int d = 1; d < 32; d <<= 1) {
                int z = __shfl_up_sync(0xffffffffu, y, d);
                if (lane >= d) y += z;
            }
            wsum[lane] = y;
        }
        __syncthreads();
        int excl = xv - v + (w > 0 ? wsum[w - 1] : 0) + carry;
        if (i < N_NODES) { g_off[i] = excl; g_cur[i] = excl; }
        carry += wsum[31];
        __syncthreads();
    }
}

// 4) scatter src indices into dst-sorted order (counting sort)
__global__ void k_scatter(const int* __restrict__ ei) {
    int e = blockIdx.x * blockDim.x + threadIdx.x;
    if (e < N_EDGES) {
        int d = ei[N_EDGES + e];
        int p = atomicAdd(&g_cur[d], 1);
        g_ssrc[p] = ei[e];
    }
}

// 5) layer 1 fused: CSR-aggregate x (4-dim) + h1 = relu(agg@W1_rel^T + b1 + x@W1_root^T)
__global__ void k_h1(const float* __restrict__ x,
                     const float* __restrict__ W1_rel,
                     const float* __restrict__ b1,
                     const float* __restrict__ W1_root) {
    __shared__ float sWr[512], sWo[512], sb[128];
    int t = threadIdx.x;  // 128 threads
    sb[t] = b1[t];
    #pragma unroll
    for (int r = 0; r < 4; r++) {
        sWr[t + 128 * r] = W1_rel[t + 128 * r];
        sWo[t + 128 * r] = W1_root[t + 128 * r];
    }
    __syncthreads();
    int n = blockIdx.x * 128 + t;
    if (n >= N_NODES) return;

    const float4* x4 = (const float4*)x;
    float4 xi = x4[n];
    float4 ag = make_float4(0.f, 0.f, 0.f, 0.f);
    int s0 = g_off[n], c = g_cnt[n];
    for (int i = 0; i < c; i++) {
        int s = g_ssrc[s0 + i];
        float4 v = x4[s];
        ag.x += v.x; ag.y += v.y; ag.z += v.z; ag.w += v.w;
    }
    float4* out = (float4*)(g_h1 + (size_t)n * 128);
    #pragma unroll
    for (int j4 = 0; j4 < 32; j4++) {
        float o[4];
        #pragma unroll
        for (int u = 0; u < 4; u++) {
            int j = j4 * 4 + u;
            float v = sb[j];
            v += ag.x * sWr[j * 4 + 0] + ag.y * sWr[j * 4 + 1]
               + ag.z * sWr[j * 4 + 2] + ag.w * sWr[j * 4 + 3];
            v += xi.x * sWo[j * 4 + 0] + xi.y * sWo[j * 4 + 1]
               + xi.z * sWo[j * 4 + 2] + xi.w * sWo[j * 4 + 3];
            o[u] = fmaxf(v, 0.f);
        }
        out[j4] = make_float4(o[0], o[1], o[2], o[3]);
    }
}

// 6) layer 2 aggregation: warp per node, atomic-free CSR sum of h1 rows
__global__ void k_agg2() {
    int gtid = blockIdx.x * blockDim.x + threadIdx.x;
    int node = gtid >> 5;
    int lane = gtid & 31;
    if (node >= N_NODES) return;
    int s0 = g_off[node], c = g_cnt[node];
    const float4* h1v = (const float4*)g_h1;
    float4 acc = make_float4(0.f, 0.f, 0.f, 0.f);
    for (int i = 0; i < c; i++) {
        int s = g_ssrc[s0 + i];               // broadcast load across warp
        float4 v = h1v[(size_t)s * 32 + lane];
        acc.x += v.x; acc.y += v.y; acc.z += v.z; acc.w += v.w;
    }
    ((float4*)g_agg2)[(size_t)node * 32 + lane] = acc;
}

// ---------------------------------------------------------------------------
// 7) layer-2 GEMM on mma.sync tf32 with fused bias+relu+mean-pool.
//    C[m,j] = sum_k [agg2|h1][m,k] * [W2_rel|W2_root][j,k]   (Mtile=128, N=128, K=256)
//    256 threads = 8 warps, warp tile 64x32 (warp_m = wid&1, warp_n = wid>>1).
//    K walked in 8 chunks of 32; per chunk: stage A/B (tf32) in SMEM, 4 k-steps
//    of m16n8k8 per warp (4 m-subtiles x 4 n-subtiles).
#define PAD 36   // 32 + 4 word padding: conflict-free fragment LDS
__global__ __launch_bounds__(256, 2) void k_gemm_mma(const float* __restrict__ W2_rel,
                                                     const float* __restrict__ W2_root,
                                                     const float* __restrict__ b2) {
    __shared__ uint32_t As[128][PAD];
    __shared__ uint32_t Bs[128][PAD];
    __shared__ float sb2s[128];
    __shared__ float spool[128];

    int t = threadIdx.x;
    int lane = t & 31, wid = t >> 5;
    int gid = lane >> 2, tg = lane & 3;      // mma fragment coords
    int warp_m = wid & 1, warp_n = wid >> 1; // 2 x 4 warp grid
    int block_m = blockIdx.x * 128;

    if (t < 128) { sb2s[t] = b2[t]; spool[t] = 0.f; }

    float c[4][4][4];  // [m_sub][n_sub][reg]
    #pragma unroll
    for (int mt = 0; mt < 4; mt++)
        #pragma unroll
        for (int nt = 0; nt < 4; nt++)
            #pragma unroll
            for (int r = 0; r < 4; r++) c[mt][nt][r] = 0.f;

    int rr = t >> 3;          // 0..31 row within 32-row group
    int cc = (t & 7) * 4;     // word col 0,4,...,28

    #pragma unroll 1
    for (int kc = 0; kc < 8; kc++) {
        const float* Asrc = (kc < 4) ? g_agg2 : g_h1;
        const float* Bsrc = (kc < 4) ? W2_rel : W2_root;
        int kbase = (kc & 3) * 32;

        __syncthreads();   // previous chunk's mma done reading SMEM
        #pragma unroll
        for (int i = 0; i < 4; i++) {
            int row = rr + i * 32;
            int gmr = block_m + row;
            if (gmr >= N_NODES) gmr = N_NODES - 1;   // clamp; masked in epilogue
            float4 va = *(const float4*)(Asrc + (size_t)gmr * 128 + kbase + cc);
            As[row][cc + 0] = cvt_tf32_rna(va.x);
            As[row][cc + 1] = cvt_tf32_rna(va.y);
            As[row][cc + 2] = cvt_tf32_rna(va.z);
            As[row][cc + 3] = cvt_tf32_rna(va.w);
            float4 vb = *(const float4*)(Bsrc + (size_t)row * 128 + kbase + cc);
            Bs[row][cc + 0] = cvt_tf32_rna(vb.x);
            Bs[row][cc + 1] = cvt_tf32_rna(vb.y);
            Bs[row][cc + 2] = cvt_tf32_rna(vb.z);
            Bs[row][cc + 3] = cvt_tf32_rna(vb.w);
        }
        __syncthreads();

        #pragma unroll
        for (int ks = 0; ks < 4; ks++) {
            int k0 = ks * 8;
            uint32_t bf[4][2];
            #pragma unroll
            for (int nt = 0; nt < 4; nt++) {
                int col = warp_n * 32 + nt * 8 + gid;
                bf[nt][0] = Bs[col][k0 + tg];
                bf[nt][1] = Bs[col][k0 + tg + 4];
            }
            #pragma unroll
            for (int mt = 0; mt < 4; mt++) {
                int row = warp_m * 64 + mt * 16 + gid;
                uint32_t a0 = As[row][k0 + tg];
                uint32_t a1 = As[row + 8][k0 + tg];
                uint32_t a2 = As[row][k0 + tg + 4];
                uint32_t a3 = As[row + 8][k0 + tg + 4];
                #pragma unroll
                for (int nt = 0; nt < 4; nt++)
                    mma_tf32(c[mt][nt], a0, a1, a2, a3, bf[nt][0], bf[nt][1]);
            }
        }
    }

    // epilogue: bias + relu + mask invalid rows, column-sum into spool
    #pragma unroll
    for (int nt = 0; nt < 4; nt++) {
        int colg = warp_n * 32 + nt * 8 + tg * 2;
        float bias0 = sb2s[colg], bias1 = sb2s[colg + 1];
        float ps0 = 0.f, ps1 = 0.f;
        #pragma unroll
        for (int mt = 0; mt < 4; mt++) {
            int rowg = block_m + warp_m * 64 + mt * 16 + gid;
            bool v0 = rowg < N_NODES;
            bool v1 = (rowg + 8) < N_NODES;
            float e0 = fmaxf(c[mt][nt][0] + bias0, 0.f);
            float e1 = fmaxf(c[mt][nt][1] + bias1, 0.f);
            float e2 = fmaxf(c[mt][nt][2] + bias0, 0.f);
            float e3 = fmaxf(c[mt][nt][3] + bias1, 0.f);
            ps0 += (v0 ? e0 : 0.f) + (v1 ? e2 : 0.f);
            ps1 += (v0 ? e1 : 0.f) + (v1 ? e3 : 0.f);
        }
        // reduce over gid (lane bits 2..4)
        #pragma unroll
        for (int d = 4; d < 32; d <<= 1) {
            ps0 += __shfl_xor_sync(0xffffffffu, ps0, d);
            ps1 += __shfl_xor_sync(0xffffffffu, ps1, d);
        }
        if (lane < 4) {
            atomicAdd(&spool[colg], ps0);
            atomicAdd(&spool[colg + 1], ps1);
        }
    }
    __syncthreads();
    if (t < 128) atomicAdd(&g_pool[t], spool[t]);
}

// 8) final head: out = (pool/N) @ Wlin^T + blin
__global__ void k_final(const float* __restrict__ Wlin,
                        const float* __restrict__ blin,
                        float* __restrict__ out) {
    __shared__ float s0[128], s1[128];
    int l = threadIdx.x;  // 128 threads
    float g = g_pool[l] * (1.0f / (float)N_NODES);
    s0[l] = g * Wlin[l];
    s1[l] = g * Wlin[128 + l];
    __syncthreads();
    for (int st = 64; st > 0; st >>= 1) {
        if (l < st) { s0[l] += s0[l + st]; s1[l] += s1[l + st]; }
        __syncthreads();
    }
    if (l == 0) {
        out[0] = s0[0] + blin[0];
        out[1] = s1[0] + blin[1];
    }
}

// ---------------------------------------------------------------------------
extern "C" void kernel_launch(void* const* d_in, const int* in_sizes, int n_in,
                              void* d_out, int out_size) {
    const float* x       = (const float*)d_in[0];
    const int*   ei      = (const int*)  d_in[1];
    const float* W1_rel  = (const float*)d_in[2];
    const float* b1      = (const float*)d_in[3];
    const float* W1_root = (const float*)d_in[4];
    const float* W2_rel  = (const float*)d_in[5];
    const float* b2      = (const float*)d_in[6];
    const float* W2_root = (const float*)d_in[7];
    const float* Wlin    = (const float*)d_in[8];
    const float* blin    = (const float*)d_in[9];
    float* out = (float*)d_out;

    k_init    <<<(N_NODES + 255) / 256, 256>>>();
    k_hist    <<<(N_EDGES + 255) / 256, 256>>>(ei);
    k_scan    <<<1, 1024>>>();
    k_scatter <<<(N_EDGES + 255) / 256, 256>>>(ei);
    k_h1      <<<(N_NODES + 127) / 128, 128>>>(x, W1_rel, b1, W1_root);
    k_agg2    <<<(N_NODES * 32 + 255) / 256, 256>>>();
    k_gemm_mma<<<(N_NODES + 127) / 128, 256>>>(W2_rel, W2_root, b2);
    k_final   <<<1, 128>>>(Wlin, blin, out);
}